// round 1
// baseline (speedup 1.0000x reference)
#include <cuda_runtime.h>
#include <cstdint>

// GCN: 3 layers, N=50000, E=600000, D=128.
// Out layout: [total | x0 | x1 | x2 | x3], each n*D f32.

#define DD 128
#define MAXN 50000
#define MAXE 600000

// Scratch (device globals; no allocation allowed)
__device__ float g_y[(size_t)MAXN * DD];    // GEMM result per layer
__device__ int   g_src[MAXE];
__device__ int   g_dst[MAXE];
__device__ float g_norm[MAXE];
__device__ float g_dinv[MAXN];
__device__ int   g_deg[MAXN];
__device__ int   g_is64;

// ---------------------------------------------------------------------------
// Detect whether edge_index buffer is int64 or int32.
// int64 little-endian with values < 50000 => every odd 32-bit word is 0.
__global__ void k_detect(const unsigned int* __restrict__ raw) {
    if (threadIdx.x == 0 && blockIdx.x == 0) {
        int ok64 = (raw[1] == 0u) && (raw[3] == 0u) && (raw[5] == 0u) &&
                   (raw[7] == 0u) && (raw[9] == 0u) && (raw[11] == 0u);
        g_is64 = ok64 ? 1 : 0;
    }
}

// Convert raw edge_index (either dtype) into int32 g_src/g_dst.
__global__ void k_convert(const void* __restrict__ raw, int E) {
    int e = blockIdx.x * blockDim.x + threadIdx.x;
    if (e >= E) return;
    int s, d;
    if (g_is64) {
        const long long* p = (const long long*)raw;
        s = (int)p[e];
        d = (int)p[e + E];
    } else {
        const int* p = (const int*)raw;
        s = p[e];
        d = p[e + E];
    }
    g_src[e] = s;
    g_dst[e] = d;
}

__global__ void k_deg_init(int n) {
    int i = blockIdx.x * blockDim.x + threadIdx.x;
    if (i < n) g_deg[i] = 1;  // self loop
}

__global__ void k_deg(int E) {
    int e = blockIdx.x * blockDim.x + threadIdx.x;
    if (e < E) atomicAdd(&g_deg[g_dst[e]], 1);
}

__global__ void k_dinv(int n) {
    int i = blockIdx.x * blockDim.x + threadIdx.x;
    if (i < n) g_dinv[i] = rsqrtf((float)g_deg[i]);
}

__global__ void k_norm(int E) {
    int e = blockIdx.x * blockDim.x + threadIdx.x;
    if (e < E) g_norm[e] = g_dinv[g_src[e]] * g_dinv[g_dst[e]];
}

// Copy x0 = item_emb[-n:] into its output slot (float4).
__global__ void k_copy_x0(const float* __restrict__ src, float* __restrict__ dst, int n) {
    int i = blockIdx.x * blockDim.x + threadIdx.x;
    int total = n * (DD / 4);
    if (i < total) ((float4*)dst)[i] = ((const float4*)src)[i];
}

// ---------------------------------------------------------------------------
// GEMM: g_y = x @ W   (x: [n,128], W: [128,128] row-major)
// BM=64, BK=32, BN=128; 256 threads; each thread: 4 rows x 8 cols.
__global__ __launch_bounds__(256) void k_gemm(const float* __restrict__ x,
                                              const float* __restrict__ W, int n) {
    __shared__ float xs[64 * 33];
    __shared__ float ws[32 * 128];
    int tid = threadIdx.x;
    int tc = tid & 15;   // col group: cols tc*8 .. tc*8+7
    int tr = tid >> 4;   // row group: rows tr*4 .. tr*4+3
    int row0 = blockIdx.x * 64;

    float acc[4][8];
#pragma unroll
    for (int i = 0; i < 4; i++)
#pragma unroll
        for (int j = 0; j < 8; j++) acc[i][j] = 0.0f;

    for (int k0 = 0; k0 < DD; k0 += 32) {
        // load x tile: 64 rows x 32 cols = 512 float4, 2 per thread
#pragma unroll
        for (int i = 0; i < 2; i++) {
            int idx = tid + i * 256;         // 0..511
            int r = idx >> 3, f = idx & 7;   // row 0..63, float4 0..7
            int grow = row0 + r;
            float4 v = make_float4(0.f, 0.f, 0.f, 0.f);
            if (grow < n) v = *(const float4*)(x + (size_t)grow * DD + k0 + f * 4);
            float* p = &xs[r * 33 + f * 4];
            p[0] = v.x; p[1] = v.y; p[2] = v.z; p[3] = v.w;
        }
        // load W tile: 32 rows x 128 cols = 1024 float4, 4 per thread
#pragma unroll
        for (int i = 0; i < 4; i++) {
            int idx = tid + i * 256;           // 0..1023
            int k = idx >> 5, f = idx & 31;    // k 0..31, float4 0..31
            *(float4*)&ws[k * 128 + f * 4] =
                *(const float4*)(W + (size_t)(k0 + k) * DD + f * 4);
        }
        __syncthreads();

#pragma unroll
        for (int k = 0; k < 32; k++) {
            float a[4];
#pragma unroll
            for (int i = 0; i < 4; i++) a[i] = xs[(tr * 4 + i) * 33 + k];
            float4 b0 = *(float4*)&ws[k * 128 + tc * 8];
            float4 b1 = *(float4*)&ws[k * 128 + tc * 8 + 4];
            float bb[8] = {b0.x, b0.y, b0.z, b0.w, b1.x, b1.y, b1.z, b1.w};
#pragma unroll
            for (int i = 0; i < 4; i++)
#pragma unroll
                for (int j = 0; j < 8; j++)
                    acc[i][j] = fmaf(a[i], bb[j], acc[i][j]);
        }
        __syncthreads();
    }

#pragma unroll
    for (int i = 0; i < 4; i++) {
        int grow = row0 + tr * 4 + i;
        if (grow < n) {
            float4 v0 = make_float4(acc[i][0], acc[i][1], acc[i][2], acc[i][3]);
            float4 v1 = make_float4(acc[i][4], acc[i][5], acc[i][6], acc[i][7]);
            *(float4*)(g_y + (size_t)grow * DD + tc * 8)     = v0;
            *(float4*)(g_y + (size_t)grow * DD + tc * 8 + 4) = v1;
        }
    }
}

// x_next = bias + y * dinv^2  (self-loop contribution + bias init)
__global__ void k_init_next(const float* __restrict__ b, float* __restrict__ xn, int n) {
    int idx = blockIdx.x * blockDim.x + threadIdx.x;  // over n*32 float4s
    if (idx >= n * 32) return;
    int i = idx >> 5, c = idx & 31;
    float s = g_dinv[i];
    s = s * s;
    float4 v = ((const float4*)g_y)[(size_t)i * 32 + c];
    float4 bb = ((const float4*)b)[c];
    float4 o = make_float4(fmaf(v.x, s, bb.x), fmaf(v.y, s, bb.y),
                           fmaf(v.z, s, bb.z), fmaf(v.w, s, bb.w));
    ((float4*)xn)[(size_t)i * 32 + c] = o;
}

// Edge scatter: x_next[dst] += y[src] * norm.  One warp per edge; lane handles
// one float4 via vector reduction (red.global.add.v4.f32).
__global__ __launch_bounds__(256) void k_scatter(float* __restrict__ xn, int E) {
    int t = blockIdx.x * blockDim.x + threadIdx.x;
    int e = t >> 5, lane = t & 31;
    if (e >= E) return;
    int s = g_src[e], d = g_dst[e];
    float nrm = g_norm[e];
    float4 v = ((const float4*)g_y)[(size_t)s * 32 + lane];
    float* p = xn + (size_t)d * DD + lane * 4;
    asm volatile("red.global.add.v4.f32 [%0], {%1, %2, %3, %4};"
                 :: "l"(p), "f"(v.x * nrm), "f"(v.y * nrm),
                    "f"(v.z * nrm), "f"(v.w * nrm)
                 : "memory");
}

// total = x0 + x1 + x2 + x3
__global__ void k_total(float* __restrict__ out, int n) {
    int i = blockIdx.x * blockDim.x + threadIdx.x;  // over n*32 float4s
    if (i >= n * 32) return;
    size_t nd4 = (size_t)n * 32;
    const float4* o = (const float4*)out;
    float4 a = o[nd4 + i], b = o[2 * nd4 + i], c = o[3 * nd4 + i], d = o[4 * nd4 + i];
    ((float4*)out)[i] = make_float4(a.x + b.x + c.x + d.x,
                                    a.y + b.y + c.y + d.y,
                                    a.z + b.z + c.z + d.z,
                                    a.w + b.w + c.w + d.w);
}

// ---------------------------------------------------------------------------
extern "C" void kernel_launch(void* const* d_in, const int* in_sizes, int n_in,
                              void* d_out, int out_size) {
    const float* item_emb = (const float*)d_in[0];  // [80000,128]
    const float* weights  = (const float*)d_in[1];  // [3,128,128]
    const float* biases   = (const float*)d_in[2];  // [3,128]
    const void*  edge_raw = d_in[3];                // [2,E] int64 or int32

    int n = out_size / (5 * DD);            // 50000
    int E = in_sizes[3] / 2;                // 600000
    int emb_off = in_sizes[0] - n * DD;     // skip first (table - n) rows
    float* out = (float*)d_out;

    const int TB = 256;
    int nb_n   = (n + TB - 1) / TB;
    int nb_e   = (E + TB - 1) / TB;
    int nb_nd4 = (n * 32 + TB - 1) / TB;

    // Graph preprocessing
    k_detect<<<1, 32>>>((const unsigned int*)edge_raw);
    k_convert<<<nb_e, TB>>>(edge_raw, E);
    k_deg_init<<<nb_n, TB>>>(n);
    k_deg<<<nb_e, TB>>>(E);
    k_dinv<<<nb_n, TB>>>(n);
    k_norm<<<nb_e, TB>>>(E);

    // x0
    k_copy_x0<<<nb_nd4, TB>>>(item_emb + emb_off, out + (size_t)n * DD, n);

    // Layers
    long long sc_threads = (long long)E * 32;
    int nb_sc = (int)((sc_threads + TB - 1) / TB);
    for (int l = 0; l < 3; l++) {
        const float* xin = out + (size_t)(l + 1) * n * DD;
        float* xout      = out + (size_t)(l + 2) * n * DD;
        k_gemm<<<(n + 63) / 64, 256>>>(xin, weights + (size_t)l * DD * DD, n);
        k_init_next<<<nb_nd4, TB>>>(biases + (size_t)l * DD, xout, n);
        k_scatter<<<nb_sc, TB>>>(xout, E);
    }

    // total
    k_total<<<nb_nd4, TB>>>(out, n);
}

// round 2
// speedup vs baseline: 1.2966x; 1.2966x over previous
#include <cuda_runtime.h>
#include <cstdint>

// GCN: 3 layers, N=50000, E=600000, D=128.
// Out layout: [total | x0 | x1 | x2 | x3], each n*D f32.

#define DD 128
#define MAXN 50016
#define MAXE 600000
#define SCAN_B 512

// Scratch (device globals; no allocation allowed)
__device__ float g_y[(size_t)MAXN * DD];    // GEMM result per layer
__device__ int   g_src[MAXE];
__device__ int   g_dst[MAXE];
__device__ int   g_csrc[MAXE];              // CSR: src per slot
__device__ float g_cw[MAXE];                // CSR: edge weight (norm)
__device__ float g_dinv[MAXN];
__device__ int   g_deg[MAXN];               // real in-edges (no self loop)
__device__ int   g_rowstart[MAXN];
__device__ int   g_cursor[MAXN];
__device__ int   g_bsum[256];
__device__ int   g_boff[256];
__device__ int   g_is64;

// ---------------------------------------------------------------------------
// Detect int64 vs int32 edge_index (LE int64 < 50000 => odd words zero).
__global__ void k_detect(const unsigned int* __restrict__ raw) {
    if (threadIdx.x == 0 && blockIdx.x == 0) {
        int ok64 = (raw[1] == 0u) && (raw[3] == 0u) && (raw[5] == 0u) &&
                   (raw[7] == 0u) && (raw[9] == 0u) && (raw[11] == 0u);
        g_is64 = ok64 ? 1 : 0;
    }
}

__global__ void k_zero_deg(int n) {
    int i = blockIdx.x * blockDim.x + threadIdx.x;
    if (i < n) g_deg[i] = 0;
}

// Convert edges to int32 and count in-degree in one pass.
__global__ void k_convert_deg(const void* __restrict__ raw, int E) {
    int e = blockIdx.x * blockDim.x + threadIdx.x;
    if (e >= E) return;
    int s, d;
    if (g_is64) {
        const long long* p = (const long long*)raw;
        s = (int)p[e];
        d = (int)p[e + E];
    } else {
        const int* p = (const int*)raw;
        s = p[e];
        d = p[e + E];
    }
    g_src[e] = s;
    g_dst[e] = d;
    atomicAdd(&g_deg[d], 1);
}

__global__ void k_dinv(int n) {
    int i = blockIdx.x * blockDim.x + threadIdx.x;
    if (i < n) g_dinv[i] = rsqrtf((float)(g_deg[i] + 1));  // +1 self loop
}

// --- exclusive scan of g_deg into g_rowstart (3 kernels) ---
__global__ void k_scan1(int n) {
    __shared__ int sh[SCAN_B];
    int i = blockIdx.x * SCAN_B + threadIdx.x;
    int v = (i < n) ? g_deg[i] : 0;
    sh[threadIdx.x] = v;
    __syncthreads();
#pragma unroll
    for (int off = 1; off < SCAN_B; off <<= 1) {
        int t = (threadIdx.x >= off) ? sh[threadIdx.x - off] : 0;
        __syncthreads();
        sh[threadIdx.x] += t;
        __syncthreads();
    }
    if (i < n) g_rowstart[i] = sh[threadIdx.x] - v;  // exclusive
    if (threadIdx.x == SCAN_B - 1) g_bsum[blockIdx.x] = sh[SCAN_B - 1];
}

__global__ void k_scan2(int nb) {
    if (threadIdx.x == 0) {
        int run = 0;
        for (int b = 0; b < nb; b++) { g_boff[b] = run; run += g_bsum[b]; }
    }
}

__global__ void k_scan3(int n) {
    int i = blockIdx.x * blockDim.x + threadIdx.x;
    if (i < n) {
        int v = g_rowstart[i] + g_boff[i >> 9];
        g_rowstart[i] = v;
        g_cursor[i]   = v;
    }
}

// Fill CSR slots; edge weight = dinv[src]*dinv[dst].
__global__ void k_fill(int E) {
    int e = blockIdx.x * blockDim.x + threadIdx.x;
    if (e >= E) return;
    int s = g_src[e], d = g_dst[e];
    int pos = atomicAdd(&g_cursor[d], 1);
    g_csrc[pos] = s;
    g_cw[pos]   = g_dinv[s] * g_dinv[d];
}

// Copy x0 = item_emb[-n:] into its output slot (float4).
__global__ void k_copy_x0(const float* __restrict__ src, float* __restrict__ dst, int n) {
    int i = blockIdx.x * blockDim.x + threadIdx.x;
    if (i < n * (DD / 4)) ((float4*)dst)[i] = ((const float4*)src)[i];
}

// ---------------------------------------------------------------------------
// GEMM: g_y = x @ W   (x: [n,128], W: [128,128] row-major)
// BM=64, BK=32, BN=128; 256 threads; each thread: 4 rows x 8 cols.
__global__ __launch_bounds__(256) void k_gemm(const float* __restrict__ x,
                                              const float* __restrict__ W, int n) {
    __shared__ float xs[64 * 33];
    __shared__ float ws[32 * 128];
    int tid = threadIdx.x;
    int tc = tid & 15;
    int tr = tid >> 4;
    int row0 = blockIdx.x * 64;

    float acc[4][8];
#pragma unroll
    for (int i = 0; i < 4; i++)
#pragma unroll
        for (int j = 0; j < 8; j++) acc[i][j] = 0.0f;

    for (int k0 = 0; k0 < DD; k0 += 32) {
#pragma unroll
        for (int i = 0; i < 2; i++) {
            int idx = tid + i * 256;
            int r = idx >> 3, f = idx & 7;
            int grow = row0 + r;
            float4 v = make_float4(0.f, 0.f, 0.f, 0.f);
            if (grow < n) v = *(const float4*)(x + (size_t)grow * DD + k0 + f * 4);
            float* p = &xs[r * 33 + f * 4];
            p[0] = v.x; p[1] = v.y; p[2] = v.z; p[3] = v.w;
        }
#pragma unroll
        for (int i = 0; i < 4; i++) {
            int idx = tid + i * 256;
            int k = idx >> 5, f = idx & 31;
            *(float4*)&ws[k * 128 + f * 4] =
                *(const float4*)(W + (size_t)(k0 + k) * DD + f * 4);
        }
        __syncthreads();

#pragma unroll
        for (int k = 0; k < 32; k++) {
            float a[4];
#pragma unroll
            for (int i = 0; i < 4; i++) a[i] = xs[(tr * 4 + i) * 33 + k];
            float4 b0 = *(float4*)&ws[k * 128 + tc * 8];
            float4 b1 = *(float4*)&ws[k * 128 + tc * 8 + 4];
            float bb[8] = {b0.x, b0.y, b0.z, b0.w, b1.x, b1.y, b1.z, b1.w};
#pragma unroll
            for (int i = 0; i < 4; i++)
#pragma unroll
                for (int j = 0; j < 8; j++)
                    acc[i][j] = fmaf(a[i], bb[j], acc[i][j]);
        }
        __syncthreads();
    }

#pragma unroll
    for (int i = 0; i < 4; i++) {
        int grow = row0 + tr * 4 + i;
        if (grow < n) {
            *(float4*)(g_y + (size_t)grow * DD + tc * 8) =
                make_float4(acc[i][0], acc[i][1], acc[i][2], acc[i][3]);
            *(float4*)(g_y + (size_t)grow * DD + tc * 8 + 4) =
                make_float4(acc[i][4], acc[i][5], acc[i][6], acc[i][7]);
        }
    }
}

// ---------------------------------------------------------------------------
// Aggregate: xout[i] = bias + y[i]*dinv[i]^2 + sum_e y[src_e]*w_e
// One warp per node; lane handles one float4 column. No atomics.
__global__ __launch_bounds__(256) void k_aggregate(const float* __restrict__ bias,
                                                   float* __restrict__ xout, int n) {
    int t = blockIdx.x * blockDim.x + threadIdx.x;
    int node = t >> 5, lane = t & 31;
    if (node >= n) return;

    float s = g_dinv[node];
    s = s * s;
    float4 bb = ((const float4*)bias)[lane];
    float4 v  = ((const float4*)g_y)[(size_t)node * 32 + lane];
    float ax = fmaf(v.x, s, bb.x);
    float ay = fmaf(v.y, s, bb.y);
    float az = fmaf(v.z, s, bb.z);
    float aw = fmaf(v.w, s, bb.w);

    int st  = g_rowstart[node];
    int cnt = g_deg[node];
    int k = 0;
    // software-pipelined by 2 for MLP
    for (; k + 1 < cnt; k += 2) {
        int   s0 = g_csrc[st + k],     s1 = g_csrc[st + k + 1];
        float w0 = g_cw[st + k],       w1 = g_cw[st + k + 1];
        float4 v0 = ((const float4*)g_y)[(size_t)s0 * 32 + lane];
        float4 v1 = ((const float4*)g_y)[(size_t)s1 * 32 + lane];
        ax = fmaf(v0.x, w0, ax); ay = fmaf(v0.y, w0, ay);
        az = fmaf(v0.z, w0, az); aw = fmaf(v0.w, w0, aw);
        ax = fmaf(v1.x, w1, ax); ay = fmaf(v1.y, w1, ay);
        az = fmaf(v1.z, w1, az); aw = fmaf(v1.w, w1, aw);
    }
    if (k < cnt) {
        int   s0 = g_csrc[st + k];
        float w0 = g_cw[st + k];
        float4 v0 = ((const float4*)g_y)[(size_t)s0 * 32 + lane];
        ax = fmaf(v0.x, w0, ax); ay = fmaf(v0.y, w0, ay);
        az = fmaf(v0.z, w0, az); aw = fmaf(v0.w, w0, aw);
    }
    ((float4*)xout)[(size_t)node * 32 + lane] = make_float4(ax, ay, az, aw);
}

// total = x0 + x1 + x2 + x3
__global__ void k_total(float* __restrict__ out, int n) {
    int i = blockIdx.x * blockDim.x + threadIdx.x;
    if (i >= n * 32) return;
    size_t nd4 = (size_t)n * 32;
    const float4* o = (const float4*)out;
    float4 a = o[nd4 + i], b = o[2 * nd4 + i], c = o[3 * nd4 + i], d = o[4 * nd4 + i];
    ((float4*)out)[i] = make_float4(a.x + b.x + c.x + d.x,
                                    a.y + b.y + c.y + d.y,
                                    a.z + b.z + c.z + d.z,
                                    a.w + b.w + c.w + d.w);
}

// ---------------------------------------------------------------------------
extern "C" void kernel_launch(void* const* d_in, const int* in_sizes, int n_in,
                              void* d_out, int out_size) {
    const float* item_emb = (const float*)d_in[0];  // [80000,128]
    const float* weights  = (const float*)d_in[1];  // [3,128,128]
    const float* biases   = (const float*)d_in[2];  // [3,128]
    const void*  edge_raw = d_in[3];                // [2,E] int64 or int32

    int n = out_size / (5 * DD);            // 50000
    int E = in_sizes[3] / 2;                // 600000
    int emb_off = in_sizes[0] - n * DD;
    float* out = (float*)d_out;

    const int TB = 256;
    int nb_n    = (n + TB - 1) / TB;
    int nb_e    = (E + TB - 1) / TB;
    int nb_nd4  = (n * 32 + TB - 1) / TB;
    int nb_scan = (n + SCAN_B - 1) / SCAN_B;

    // Graph preprocessing -> CSR
    k_detect<<<1, 32>>>((const unsigned int*)edge_raw);
    k_zero_deg<<<nb_n, TB>>>(n);
    k_convert_deg<<<nb_e, TB>>>(edge_raw, E);
    k_dinv<<<nb_n, TB>>>(n);
    k_scan1<<<nb_scan, SCAN_B>>>(n);
    k_scan2<<<1, 32>>>(nb_scan);
    k_scan3<<<nb_n, TB>>>(n);
    k_fill<<<nb_e, TB>>>(E);

    // x0
    k_copy_x0<<<nb_nd4, TB>>>(item_emb + emb_off, out + (size_t)n * DD, n);

    // Layers
    long long agg_threads = (long long)n * 32;
    int nb_agg = (int)((agg_threads + TB - 1) / TB);
    for (int l = 0; l < 3; l++) {
        const float* xin = out + (size_t)(l + 1) * n * DD;
        float* xout      = out + (size_t)(l + 2) * n * DD;
        k_gemm<<<(n + 63) / 64, 256>>>(xin, weights + (size_t)l * DD * DD, n);
        k_aggregate<<<nb_agg, TB>>>(biases + (size_t)l * DD, xout, n);
    }

    // total
    k_total<<<nb_nd4, TB>>>(out, n);
}

// round 4
// speedup vs baseline: 2.2807x; 1.7589x over previous
#include <cuda_runtime.h>
#include <cuda_bf16.h>
#include <cstdint>

// GCN: 3 layers, N=50000, E=600000, D=128.
// Out layout: [total | x0 | x1 | x2 | x3], each n*D f32.
// GEMM via mma.sync bf16 split-precision (hi/lo, 3 products, fp32 accum).

#define DD 128
#define MAXN 50016
#define MAXE 600000
#define SCAN_B 512
#define LDT 136            // padded row length (bf16 elems) for ldmatrix tiles

// Scratch (device globals; no allocation allowed)
__device__ float g_y[(size_t)MAXN * DD];
__device__ int   g_src[MAXE];
__device__ int   g_dst[MAXE];
__device__ int   g_csrc[MAXE];
__device__ float g_cw[MAXE];
__device__ float g_dinv[MAXN];
__device__ int   g_deg[MAXN];
__device__ int   g_rowstart[MAXN];
__device__ int   g_cursor[MAXN];
__device__ int   g_bsum[256];
__device__ int   g_boff[256];
__device__ int   g_is64;

// ---------------------------------------------------------------------------
__device__ __forceinline__ uint32_t smem_u32(const void* p) {
    uint32_t a;
    asm("{ .reg .u64 t; cvta.to.shared.u64 t, %1; cvt.u32.u64 %0, t; }" : "=r"(a) : "l"(p));
    return a;
}
__device__ __forceinline__ void ldm_x4(uint32_t* r, uint32_t addr) {
    asm volatile("ldmatrix.sync.aligned.m8n8.x4.shared.b16 {%0,%1,%2,%3}, [%4];"
                 : "=r"(r[0]), "=r"(r[1]), "=r"(r[2]), "=r"(r[3]) : "r"(addr));
}
__device__ __forceinline__ void ldm_x4_t(uint32_t* r, uint32_t addr) {
    asm volatile("ldmatrix.sync.aligned.m8n8.x4.trans.shared.b16 {%0,%1,%2,%3}, [%4];"
                 : "=r"(r[0]), "=r"(r[1]), "=r"(r[2]), "=r"(r[3]) : "r"(addr));
}
__device__ __forceinline__ void mma_bf16(float* c, const uint32_t* a, const uint32_t* b) {
    asm volatile(
        "mma.sync.aligned.m16n8k16.row.col.f32.bf16.bf16.f32 "
        "{%0,%1,%2,%3}, {%4,%5,%6,%7}, {%8,%9}, {%0,%1,%2,%3};"
        : "+f"(c[0]), "+f"(c[1]), "+f"(c[2]), "+f"(c[3])
        : "r"(a[0]), "r"(a[1]), "r"(a[2]), "r"(a[3]), "r"(b[0]), "r"(b[1]));
}
__device__ __forceinline__ uint32_t bfbits(float v) {
    return (uint32_t)__bfloat16_as_ushort(__float2bfloat16(v));
}
__device__ __forceinline__ float bfval(uint32_t b) {
    return __bfloat162float(__ushort_as_bfloat16((unsigned short)b));
}

// smem: AH[128][136] AL BH BL (bf16)
#define T_ELE (128 * LDT)
#define GEMM_SMEM (4 * T_ELE * 2)

// ---------------------------------------------------------------------------
// GEMM: g_y = x @ W via HMMA. One CTA per 128 rows; 256 threads (8 warps),
// warp w computes rows w*16..w*16+15 over all 128 output cols.
__global__ __launch_bounds__(256) void k_gemm_mma(const float* __restrict__ x,
                                                  const float* __restrict__ W, int n) {
    extern __shared__ __align__(16) char smem[];
    __nv_bfloat16* AH = (__nv_bfloat16*)smem;
    __nv_bfloat16* AL = AH + T_ELE;
    __nv_bfloat16* BH = AL + T_ELE;
    __nv_bfloat16* BL = BH + T_ELE;

    int tid = threadIdx.x;
    int wid = tid >> 5, lane = tid & 31;
    int row0 = blockIdx.x * 128;

    // Convert x tile -> AH/AL  (each warp handles full rows; 16 float4/thread)
#pragma unroll
    for (int i = 0; i < 16; i++) {
        int idx = tid + i * 256;          // 0..4095
        int r = idx >> 5, f = idx & 31;
        int grow = row0 + r;
        float4 v = make_float4(0.f, 0.f, 0.f, 0.f);
        if (grow < n) v = *(const float4*)(x + (size_t)grow * DD + f * 4);
        uint32_t hx = bfbits(v.x), hy = bfbits(v.y), hz = bfbits(v.z), hw = bfbits(v.w);
        uint2 hh = make_uint2((hy << 16) | hx, (hw << 16) | hz);
        uint2 ll = make_uint2((bfbits(v.y - bfval(hy)) << 16) | bfbits(v.x - bfval(hx)),
                              (bfbits(v.w - bfval(hw)) << 16) | bfbits(v.z - bfval(hz)));
        *(uint2*)(AH + r * LDT + f * 4) = hh;
        *(uint2*)(AL + r * LDT + f * 4) = ll;
    }
    // Convert W -> BH/BL (row-major [k][n])
#pragma unroll
    for (int i = 0; i < 16; i++) {
        int idx = tid + i * 256;
        int r = idx >> 5, f = idx & 31;
        float4 v = *(const float4*)(W + (size_t)r * DD + f * 4);
        uint32_t hx = bfbits(v.x), hy = bfbits(v.y), hz = bfbits(v.z), hw = bfbits(v.w);
        uint2 hh = make_uint2((hy << 16) | hx, (hw << 16) | hz);
        uint2 ll = make_uint2((bfbits(v.y - bfval(hy)) << 16) | bfbits(v.x - bfval(hx)),
                              (bfbits(v.w - bfval(hw)) << 16) | bfbits(v.z - bfval(hz)));
        *(uint2*)(BH + r * LDT + f * 4) = hh;
        *(uint2*)(BL + r * LDT + f * 4) = ll;
    }
    __syncthreads();

    // Fragment addresses
    int m0 = wid * 16;
    uint32_t a_off_h = smem_u32(AH + (m0 + (lane & 15)) * LDT + (lane >> 4) * 8);
    uint32_t a_off_l = a_off_h + (uint32_t)(T_ELE * 2);

    float acc[16][4];
#pragma unroll
    for (int j = 0; j < 16; j++)
#pragma unroll
        for (int q = 0; q < 4; q++) acc[j][q] = 0.0f;

#pragma unroll
    for (int k = 0; k < 8; k++) {
        uint32_t ah[4], al[4];
        ldm_x4(ah, a_off_h + k * 32);   // k*16 bf16 = 32 bytes
        ldm_x4(al, a_off_l + k * 32);

        // B row base for this k: rows k*16 + (lane&15), col (lane>>4)*8 + n0
        uint32_t b_base = smem_u32(BH + (k * 16 + (lane & 15)) * LDT + (lane >> 4) * 8);
#pragma unroll
        for (int j2 = 0; j2 < 8; j2++) {            // n16 tiles
            uint32_t bh[4], bl[4];
            ldm_x4_t(bh, b_base + j2 * 32);         // +16 cols = 32 bytes
            ldm_x4_t(bl, b_base + j2 * 32 + (uint32_t)(T_ELE * 2));
            // n8 tile 2*j2   : frags {bh[0],bh[1]}
            mma_bf16(acc[2 * j2],     ah, bh);
            mma_bf16(acc[2 * j2],     ah, bl);
            mma_bf16(acc[2 * j2],     al, bh);
            // n8 tile 2*j2+1 : frags {bh[2],bh[3]}
            mma_bf16(acc[2 * j2 + 1], ah, bh + 2);
            mma_bf16(acc[2 * j2 + 1], ah, bl + 2);
            mma_bf16(acc[2 * j2 + 1], al, bh + 2);
        }
    }

    // Epilogue: write g_y
    int r_lo = row0 + m0 + (lane >> 2);
    int r_hi = r_lo + 8;
    int cbase = (lane & 3) * 2;
#pragma unroll
    for (int j = 0; j < 16; j++) {
        int col = j * 8 + cbase;
        if (r_lo < n) *(float2*)(g_y + (size_t)r_lo * DD + col) = make_float2(acc[j][0], acc[j][1]);
        if (r_hi < n) *(float2*)(g_y + (size_t)r_hi * DD + col) = make_float2(acc[j][2], acc[j][3]);
    }
}

// ---------------------------------------------------------------------------
// Preprocessing
__global__ void k_detect(const unsigned int* __restrict__ raw) {
    if (threadIdx.x == 0 && blockIdx.x == 0) {
        int ok64 = (raw[1] == 0u) && (raw[3] == 0u) && (raw[5] == 0u) &&
                   (raw[7] == 0u) && (raw[9] == 0u) && (raw[11] == 0u);
        g_is64 = ok64 ? 1 : 0;
    }
}

__global__ void k_zero_deg(int n) {
    int i = blockIdx.x * blockDim.x + threadIdx.x;
    if (i < n) g_deg[i] = 0;
}

__global__ void k_convert_deg(const void* __restrict__ raw, int E) {
    int e = blockIdx.x * blockDim.x + threadIdx.x;
    if (e >= E) return;
    int s, d;
    if (g_is64) {
        const long long* p = (const long long*)raw;
        s = (int)p[e]; d = (int)p[e + E];
    } else {
        const int* p = (const int*)raw;
        s = p[e]; d = p[e + E];
    }
    g_src[e] = s; g_dst[e] = d;
    atomicAdd(&g_deg[d], 1);
}

__global__ void k_dinv(int n) {
    int i = blockIdx.x * blockDim.x + threadIdx.x;
    if (i < n) g_dinv[i] = rsqrtf((float)(g_deg[i] + 1));
}

__global__ void k_scan1(int n) {
    __shared__ int sh[SCAN_B];
    int i = blockIdx.x * SCAN_B + threadIdx.x;
    int v = (i < n) ? g_deg[i] : 0;
    sh[threadIdx.x] = v;
    __syncthreads();
#pragma unroll
    for (int off = 1; off < SCAN_B; off <<= 1) {
        int t = (threadIdx.x >= off) ? sh[threadIdx.x - off] : 0;
        __syncthreads();
        sh[threadIdx.x] += t;
        __syncthreads();
    }
    if (i < n) g_rowstart[i] = sh[threadIdx.x] - v;
    if (threadIdx.x == SCAN_B - 1) g_bsum[blockIdx.x] = sh[SCAN_B - 1];
}

__global__ void k_scan2(int nb) {
    if (threadIdx.x == 0) {
        int run = 0;
        for (int b = 0; b < nb; b++) { g_boff[b] = run; run += g_bsum[b]; }
    }
}

__global__ void k_scan3(int n) {
    int i = blockIdx.x * blockDim.x + threadIdx.x;
    if (i < n) {
        int v = g_rowstart[i] + g_boff[i >> 9];
        g_rowstart[i] = v;
        g_cursor[i]   = v;
    }
}

__global__ void k_fill(int E) {
    int e = blockIdx.x * blockDim.x + threadIdx.x;
    if (e >= E) return;
    int s = g_src[e], d = g_dst[e];
    int pos = atomicAdd(&g_cursor[d], 1);
    g_csrc[pos] = s;
    g_cw[pos]   = g_dinv[s] * g_dinv[d];
}

__global__ void k_copy_x0(const float* __restrict__ src, float* __restrict__ dst, int n) {
    int i = blockIdx.x * blockDim.x + threadIdx.x;
    if (i < n * (DD / 4)) ((float4*)dst)[i] = ((const float4*)src)[i];
}

// ---------------------------------------------------------------------------
// Aggregate: xout[i] = bias + y[i]*dinv[i]^2 + sum_e y[src_e]*w_e (warp/node)
__global__ __launch_bounds__(256) void k_aggregate(const float* __restrict__ bias,
                                                   float* __restrict__ xout, int n) {
    int t = blockIdx.x * blockDim.x + threadIdx.x;
    int node = t >> 5, lane = t & 31;
    if (node >= n) return;

    float s = g_dinv[node];
    s = s * s;
    float4 bb = ((const float4*)bias)[lane];
    float4 v  = ((const float4*)g_y)[(size_t)node * 32 + lane];
    float ax = fmaf(v.x, s, bb.x);
    float ay = fmaf(v.y, s, bb.y);
    float az = fmaf(v.z, s, bb.z);
    float aw = fmaf(v.w, s, bb.w);

    int st  = g_rowstart[node];
    int cnt = g_deg[node];
    int k = 0;
    for (; k + 1 < cnt; k += 2) {
        int   s0 = g_csrc[st + k],     s1 = g_csrc[st + k + 1];
        float w0 = g_cw[st + k],       w1 = g_cw[st + k + 1];
        float4 v0 = ((const float4*)g_y)[(size_t)s0 * 32 + lane];
        float4 v1 = ((const float4*)g_y)[(size_t)s1 * 32 + lane];
        ax = fmaf(v0.x, w0, ax); ay = fmaf(v0.y, w0, ay);
        az = fmaf(v0.z, w0, az); aw = fmaf(v0.w, w0, aw);
        ax = fmaf(v1.x, w1, ax); ay = fmaf(v1.y, w1, ay);
        az = fmaf(v1.z, w1, az); aw = fmaf(v1.w, w1, aw);
    }
    if (k < cnt) {
        int   s0 = g_csrc[st + k];
        float w0 = g_cw[st + k];
        float4 v0 = ((const float4*)g_y)[(size_t)s0 * 32 + lane];
        ax = fmaf(v0.x, w0, ax); ay = fmaf(v0.y, w0, ay);
        az = fmaf(v0.z, w0, az); aw = fmaf(v0.w, w0, aw);
    }
    ((float4*)xout)[(size_t)node * 32 + lane] = make_float4(ax, ay, az, aw);
}

__global__ void k_total(float* __restrict__ out, int n) {
    int i = blockIdx.x * blockDim.x + threadIdx.x;
    if (i >= n * 32) return;
    size_t nd4 = (size_t)n * 32;
    const float4* o = (const float4*)out;
    float4 a = o[nd4 + i], b = o[2 * nd4 + i], c = o[3 * nd4 + i], d = o[4 * nd4 + i];
    ((float4*)out)[i] = make_float4(a.x + b.x + c.x + d.x,
                                    a.y + b.y + c.y + d.y,
                                    a.z + b.z + c.z + d.z,
                                    a.w + b.w + c.w + d.w);
}

// ---------------------------------------------------------------------------
extern "C" void kernel_launch(void* const* d_in, const int* in_sizes, int n_in,
                              void* d_out, int out_size) {
    const float* item_emb = (const float*)d_in[0];
    const float* weights  = (const float*)d_in[1];
    const float* biases   = (const float*)d_in[2];
    const void*  edge_raw = d_in[3];

    int n = out_size / (5 * DD);
    int E = in_sizes[3] / 2;
    int emb_off = in_sizes[0] - n * DD;
    float* out = (float*)d_out;

    static bool attr_set = false;
    if (!attr_set) {
        cudaFuncSetAttribute(k_gemm_mma, cudaFuncAttributeMaxDynamicSharedMemorySize, GEMM_SMEM);
        attr_set = true;
    }

    const int TB = 256;
    int nb_n    = (n + TB - 1) / TB;
    int nb_e    = (E + TB - 1) / TB;
    int nb_nd4  = (n * 32 + TB - 1) / TB;
    int nb_scan = (n + SCAN_B - 1) / SCAN_B;

    k_detect<<<1, 32>>>((const unsigned int*)edge_raw);
    k_zero_deg<<<nb_n, TB>>>(n);
    k_convert_deg<<<nb_e, TB>>>(edge_raw, E);
    k_dinv<<<nb_n, TB>>>(n);
    k_scan1<<<nb_scan, SCAN_B>>>(n);
    k_scan2<<<1, 32>>>(nb_scan);
    k_scan3<<<nb_n, TB>>>(n);
    k_fill<<<nb_e, TB>>>(E);

    k_copy_x0<<<nb_nd4, TB>>>(item_emb + emb_off, out + (size_t)n * DD, n);

    long long agg_threads = (long long)n * 32;
    int nb_agg = (int)((agg_threads + TB - 1) / TB);
    int nb_gemm = (n + 127) / 128;
    for (int l = 0; l < 3; l++) {
        const float* xin = out + (size_t)(l + 1) * n * DD;
        float* xout      = out + (size_t)(l + 2) * n * DD;
        k_gemm_mma<<<nb_gemm, 256, GEMM_SMEM>>>(xin, weights + (size_t)l * DD * DD, n);
        k_aggregate<<<nb_agg, TB>>>(biases + (size_t)l * DD, xout, n);
    }

    k_total<<<nb_nd4, TB>>>(out, n);
}